// round 7
// baseline (speedup 1.0000x reference)
#include <cuda_runtime.h>
#include <math.h>
#include <stdint.h>

#define H 4
#define Bb 8
#define Nn 1024
#define INF_ 1024
#define E 256
#define A_ 64
#define BN_ROWS 8192        /* B*N */
#define ALPHA 0.2f
#define PITCH 136           /* smem row pitch, conflict-free frags */

// ---- scratch (static device memory; no runtime allocation) ----
__device__ float g_Wh[H * BN_ROWS * E];                 // 32 MB  [h][row][e]
__device__ float g_f1[H * BN_ROWS];
__device__ float g_E1[H * BN_ROWS];
__device__ float g_F1[H * BN_ROWS];
__device__ float4 g_pack[H * BN_ROWS];                  // (f2, exp(f2), exp(.2 f2), 0)
__device__ unsigned g_adjbits[Bb * Nn * (Nn / 32)];     // 1 MB packed adjacency
__device__ float g_feat[(size_t)BN_ROWS * H * E];       // 32 MB [row][h*E+e]

// ---- tf32 helpers ----
__device__ __forceinline__ float tf32_lo(float v) {
    return v - __uint_as_float(__float_as_uint(v) & 0xFFFFE000u);
}
__device__ __forceinline__ void mma8(float c[4], const float a[4], const float b[2]) {
    asm volatile(
        "mma.sync.aligned.m16n8k8.row.col.f32.tf32.tf32.f32 "
        "{%0,%1,%2,%3}, {%4,%5,%6,%7}, {%8,%9}, {%0,%1,%2,%3};"
        : "+f"(c[0]), "+f"(c[1]), "+f"(c[2]), "+f"(c[3])
        : "r"(__float_as_uint(a[0])), "r"(__float_as_uint(a[1])),
          "r"(__float_as_uint(a[2])), "r"(__float_as_uint(a[3])),
          "r"(__float_as_uint(b[0])), "r"(__float_as_uint(b[1])));
}
// one k8 step: 16 mma tiles x 3 passes (3xTF32)
__device__ __forceinline__ void k8_step(const float (*AS)[PITCH], const float (*BS)[PITCH],
                                        int k8, int mw, int nw, int lq, int lr,
                                        float acc[4][4][4]) {
    float a[4][4], al[4][4], bf[4][2], bl[4][2];
#pragma unroll
    for (int mt = 0; mt < 4; mt++) {
        int m0 = mw + 16 * mt + lr;
        a[mt][0] = AS[k8 + lq][m0];
        a[mt][1] = AS[k8 + lq][m0 + 8];
        a[mt][2] = AS[k8 + lq + 4][m0];
        a[mt][3] = AS[k8 + lq + 4][m0 + 8];
        al[mt][0] = tf32_lo(a[mt][0]);
        al[mt][1] = tf32_lo(a[mt][1]);
        al[mt][2] = tf32_lo(a[mt][2]);
        al[mt][3] = tf32_lo(a[mt][3]);
    }
#pragma unroll
    for (int nt = 0; nt < 4; nt++) {
        int n0 = nw + 8 * nt + lr;
        bf[nt][0] = BS[k8 + lq][n0];
        bf[nt][1] = BS[k8 + lq + 4][n0];
        bl[nt][0] = tf32_lo(bf[nt][0]);
        bl[nt][1] = tf32_lo(bf[nt][1]);
    }
#pragma unroll
    for (int mt = 0; mt < 4; mt++)
#pragma unroll
        for (int nt = 0; nt < 4; nt++) mma8(acc[mt][nt], a[mt], bf[nt]);
#pragma unroll
    for (int mt = 0; mt < 4; mt++)
#pragma unroll
        for (int nt = 0; nt < 4; nt++) mma8(acc[mt][nt], a[mt], bl[nt]);
#pragma unroll
    for (int mt = 0; mt < 4; mt++)
#pragma unroll
        for (int nt = 0; nt < 4; nt++) mma8(acc[mt][nt], al[mt], bf[nt]);
}

#define GEMM_SMEM (4 * 32 * PITCH * 4)          /* As[2][32][P] + Bs[2][32][P] */
#define ATT_SMEM  (GEMM_SMEM + 256 * 4)

// ============================================================
// K0: pack adjacency int32 -> bitmask
// ============================================================
__global__ void pack_adj(const int* __restrict__ adj) {
    int idx = blockIdx.x * blockDim.x + threadIdx.x;
    unsigned m = __ballot_sync(0xffffffffu, adj[idx] > 0);
    if ((idx & 31) == 0) g_adjbits[idx >> 5] = m;
}

// ============================================================
// K1: Wh = x @ W[h], tf32 mma 3x, BK=32 double-buffered.
// grid (E/128=2, BN/128=64, H=4), 256 thr.
// ============================================================
__global__ void __launch_bounds__(256, 2) wh_gemm_mma(const float* __restrict__ x,
                                                      const float* __restrict__ W) {
    extern __shared__ float sm[];
    float (*As0)[PITCH] = (float (*)[PITCH])sm;                     // 2*32 rows
    float (*Bs0)[PITCH] = (float (*)[PITCH])(sm + 2 * 32 * PITCH);  // 2*32 rows
    int h = blockIdx.z;
    int rowBase = blockIdx.y * 128;
    int colBase = blockIdx.x * 128;
    int tid = threadIdx.x, lane = tid & 31, wid = tid >> 5;
    int lq = lane & 3, lr = lane >> 2;
    int mw = (wid & 1) * 64, nw = (wid >> 1) * 32;

    int am = tid & 127;
    int c0 = (tid >> 7) * 4;           // A chunk base (0 or 4); chunks c0..c0+3, k=4*chunk
    int bk = tid >> 5;                 // B k rows bk, bk+8, bk+16, bk+24
    int bn = (tid & 31) * 4;

    const float* Ap = x + (size_t)(rowBase + am) * INF_;
    const float* Bp = W + (size_t)h * INF_ * E + colBase;

    // prologue: fill stage 0 (k 0..31)
    {
        float (*AsW)[PITCH] = As0;
        float (*BsW)[PITCH] = Bs0;
#pragma unroll
        for (int q = 0; q < 4; q++) {
            float4 v = *(const float4*)(Ap + 4 * (c0 + q));
            AsW[4 * (c0 + q) + 0][am] = v.x; AsW[4 * (c0 + q) + 1][am] = v.y;
            AsW[4 * (c0 + q) + 2][am] = v.z; AsW[4 * (c0 + q) + 3][am] = v.w;
        }
#pragma unroll
        for (int q = 0; q < 4; q++) {
            float4 v = *(const float4*)(Bp + (size_t)(bk + 8 * q) * E + bn);
            *(float4*)&BsW[bk + 8 * q][bn] = v;
        }
    }
    __syncthreads();

    float acc[4][4][4] = {};
    for (int c = 0; c < 32; c++) {
        int cb = c & 1, nb = cb ^ 1;
        const float (*AS)[PITCH] = As0 + cb * 32;
        const float (*BS)[PITCH] = Bs0 + cb * 32;
        float (*AsW)[PITCH] = As0 + nb * 32;
        float (*BsW)[PITCH] = Bs0 + nb * 32;
        int k0n = (c + 1) * 32;
        float4 aA0, aA1, aB0, aB1;
        if (c < 31) {
            aA0 = *(const float4*)(Ap + k0n + 4 * c0);
            aA1 = *(const float4*)(Ap + k0n + 4 * (c0 + 1));
            aB0 = *(const float4*)(Bp + (size_t)(k0n + bk) * E + bn);
            aB1 = *(const float4*)(Bp + (size_t)(k0n + bk + 8) * E + bn);
        }
        k8_step(AS, BS, 0, mw, nw, lq, lr, acc);
        k8_step(AS, BS, 8, mw, nw, lq, lr, acc);
        float4 aA2, aA3, aB2, aB3;
        if (c < 31) {
            aA2 = *(const float4*)(Ap + k0n + 4 * (c0 + 2));
            aA3 = *(const float4*)(Ap + k0n + 4 * (c0 + 3));
            aB2 = *(const float4*)(Bp + (size_t)(k0n + bk + 16) * E + bn);
            aB3 = *(const float4*)(Bp + (size_t)(k0n + bk + 24) * E + bn);
        }
        k8_step(AS, BS, 16, mw, nw, lq, lr, acc);
        if (c < 31) {
            AsW[4 * c0 + 0][am] = aA0.x; AsW[4 * c0 + 1][am] = aA0.y;
            AsW[4 * c0 + 2][am] = aA0.z; AsW[4 * c0 + 3][am] = aA0.w;
            AsW[4 * c0 + 4][am] = aA1.x; AsW[4 * c0 + 5][am] = aA1.y;
            AsW[4 * c0 + 6][am] = aA1.z; AsW[4 * c0 + 7][am] = aA1.w;
            *(float4*)&BsW[bk][bn] = aB0;
            *(float4*)&BsW[bk + 8][bn] = aB1;
        }
        k8_step(AS, BS, 24, mw, nw, lq, lr, acc);
        if (c < 31) {
            AsW[4 * c0 + 8][am] = aA2.x; AsW[4 * c0 + 9][am] = aA2.y;
            AsW[4 * c0 + 10][am] = aA2.z; AsW[4 * c0 + 11][am] = aA2.w;
            AsW[4 * c0 + 12][am] = aA3.x; AsW[4 * c0 + 13][am] = aA3.y;
            AsW[4 * c0 + 14][am] = aA3.z; AsW[4 * c0 + 15][am] = aA3.w;
            *(float4*)&BsW[bk + 16][bn] = aB2;
            *(float4*)&BsW[bk + 24][bn] = aB3;
        }
        __syncthreads();
    }

    float* Cp = g_Wh + (size_t)h * BN_ROWS * E;
#pragma unroll
    for (int mt = 0; mt < 4; mt++) {
        int r = rowBase + mw + 16 * mt + lr;
#pragma unroll
        for (int nt = 0; nt < 4; nt++) {
            int cc = colBase + nw + 8 * nt + 2 * lq;
            *(float2*)(Cp + (size_t)r * E + cc) = make_float2(acc[mt][nt][0], acc[mt][nt][1]);
            *(float2*)(Cp + (size_t)(r + 8) * E + cc) = make_float2(acc[mt][nt][2], acc[mt][nt][3]);
        }
    }
}

// ============================================================
// K2: f1/f2 = Wh . a1/a2 + factored exps (+ packed f2 trio). Warp per row.
// ============================================================
__global__ void compute_f(const float* __restrict__ a1, const float* __restrict__ a2) {
    int r = (blockIdx.x * blockDim.x + threadIdx.x) >> 5;
    int lane = threadIdx.x & 31;
    int h = r >> 13;
    const float* wh = g_Wh + (size_t)r * E;
    const float* a1p = a1 + h * E;
    const float* a2p = a2 + h * E;
    float s1 = 0.f, s2 = 0.f;
#pragma unroll
    for (int i = 0; i < 8; i++) {
        int e = lane + i * 32;
        float v = wh[e];
        s1 += v * a1p[e];
        s2 += v * a2p[e];
    }
#pragma unroll
    for (int o = 16; o > 0; o >>= 1) {
        s1 += __shfl_xor_sync(0xffffffffu, s1, o);
        s2 += __shfl_xor_sync(0xffffffffu, s2, o);
    }
    if (lane == 0) {
        g_f1[r] = s1;
        g_E1[r] = __expf(s1);
        g_F1[r] = __expf(ALPHA * s1);
        g_pack[r] = make_float4(s2, __expf(s2), __expf(ALPHA * s2), 0.f);
    }
}

// ============================================================
// K3: h' = att @ Wh_b, tf32 mma 3x, BK=32; att generated on the fly
// (unnormalized), row sums in regs, normalize + elu in epilogue.
// grid (E/128=2, Nn/128=8, H*Bb=32), 256 thr.
// ============================================================
__global__ void __launch_bounds__(256, 2) att_gemm_mma() {
    extern __shared__ float sm[];
    float (*As0)[PITCH] = (float (*)[PITCH])sm;
    float (*Bs0)[PITCH] = (float (*)[PITCH])(sm + 2 * 32 * PITCH);
    float* Ssum = sm + 4 * 32 * PITCH;     // [2][128]
    int hb = blockIdx.z;
    int h = hb >> 3, b = hb & 7;
    int rowBase = blockIdx.y * 128;
    int colBase = blockIdx.x * 128;
    int base = h * BN_ROWS + b * Nn;
    int tid = threadIdx.x, lane = tid & 31, wid = tid >> 5;
    int lq = lane & 3, lr = lane >> 2;
    int mw = (wid & 1) * 64, nw = (wid >> 1) * 32;

    // generator: fixed row i per thread, j parity by tid>>7
    int ig = tid & 127;
    int jp = tid >> 7;
    int gi = base + rowBase + ig;
    float f1v = g_f1[gi], E1v = g_E1[gi], F1v = g_F1[gi];
    const unsigned* awp = g_adjbits + (size_t)(b * Nn + rowBase + ig) * (Nn / 32);
    float rsum = 0.f;

    int bk = tid >> 5;
    int bn = (tid & 31) * 4;
    const float* Bp = g_Wh + ((size_t)h * BN_ROWS + b * Nn) * E + colBase;

#define GENH(AsW, k0, LO, HI)                                                  \
    do {                                                                       \
        unsigned wb = awp[(k0) >> 5];                                          \
        _Pragma("unroll")                                                      \
        for (int it = (LO); it < (HI); it++) {                                 \
            int jl = 2 * it + jp;                                              \
            float4 p = g_pack[base + (k0) + jl];                               \
            float s = f1v + p.x;                                               \
            float n = (s > 0.f) ? E1v * p.y : F1v * p.z;                       \
            float v = ((wb >> jl) & 1u) ? n : 0.f;                             \
            rsum += v;                                                         \
            (AsW)[jl][ig] = v;                                                 \
        }                                                                      \
    } while (0)

    // prologue: stage 0
    GENH(As0, 0, 0, 8);
    GENH(As0, 0, 8, 16);
#pragma unroll
    for (int q = 0; q < 4; q++) {
        float4 v = *(const float4*)(Bp + (size_t)(bk + 8 * q) * E + bn);
        *(float4*)&Bs0[bk + 8 * q][bn] = v;
    }
    __syncthreads();

    float acc[4][4][4] = {};
    for (int c = 0; c < 32; c++) {
        int cb = c & 1, nb = cb ^ 1;
        const float (*AS)[PITCH] = As0 + cb * 32;
        const float (*BS)[PITCH] = Bs0 + cb * 32;
        float (*AsW)[PITCH] = As0 + nb * 32;
        float (*BsW)[PITCH] = Bs0 + nb * 32;
        int k0n = (c + 1) * 32;
        float4 aB0, aB1, aB2, aB3;
        if (c < 31) {
            aB0 = *(const float4*)(Bp + (size_t)(k0n + bk) * E + bn);
            aB1 = *(const float4*)(Bp + (size_t)(k0n + bk + 8) * E + bn);
            aB2 = *(const float4*)(Bp + (size_t)(k0n + bk + 16) * E + bn);
            aB3 = *(const float4*)(Bp + (size_t)(k0n + bk + 24) * E + bn);
        }
        k8_step(AS, BS, 0, mw, nw, lq, lr, acc);
        k8_step(AS, BS, 8, mw, nw, lq, lr, acc);
        if (c < 31) GENH(AsW, k0n, 0, 8);
        k8_step(AS, BS, 16, mw, nw, lq, lr, acc);
        if (c < 31) GENH(AsW, k0n, 8, 16);
        k8_step(AS, BS, 24, mw, nw, lq, lr, acc);
        if (c < 31) {
            *(float4*)&BsW[bk][bn] = aB0;
            *(float4*)&BsW[bk + 8][bn] = aB1;
            *(float4*)&BsW[bk + 16][bn] = aB2;
            *(float4*)&BsW[bk + 24][bn] = aB3;
        }
        __syncthreads();
    }
#undef GENH

    Ssum[jp * 128 + ig] = rsum;
    __syncthreads();

#pragma unroll
    for (int mt = 0; mt < 4; mt++) {
        int rl = mw + 16 * mt + lr;
        float S0 = Ssum[rl] + Ssum[128 + rl];
        float S8 = Ssum[rl + 8] + Ssum[128 + rl + 8];
        float sc0 = (S0 > 0.f) ? (1.0f / S0) : 0.f;
        float sc8 = (S8 > 0.f) ? (1.0f / S8) : 0.f;
        float* f0 = g_feat + (size_t)(b * Nn + rowBase + rl) * (H * E) + h * E + colBase;
        float* f8 = g_feat + (size_t)(b * Nn + rowBase + rl + 8) * (H * E) + h * E + colBase;
#pragma unroll
        for (int nt = 0; nt < 4; nt++) {
            int cc = nw + 8 * nt + 2 * lq;
            float v0 = acc[mt][nt][0] * sc0;
            float v1 = acc[mt][nt][1] * sc0;
            float v2 = acc[mt][nt][2] * sc8;
            float v3 = acc[mt][nt][3] * sc8;
            v0 = (v0 > 0.f) ? v0 : expm1f(v0);
            v1 = (v1 > 0.f) ? v1 : expm1f(v1);
            v2 = (v2 > 0.f) ? v2 : expm1f(v2);
            v3 = (v3 > 0.f) ? v3 : expm1f(v3);
            *(float2*)(f0 + cc) = make_float2(v0, v1);
            *(float2*)(f8 + cc) = make_float2(v2, v3);
        }
    }
}

// ============================================================
// K5: out (8192x64) = feat (8192x1024) @ W_act (1024x64) + b_act
// BM=32 (256 blocks), 256 thr, 2x4 per thread
// ============================================================
__global__ void __launch_bounds__(256) final_gemm(const float* __restrict__ W_act,
                                                  const float* __restrict__ b_act,
                                                  float* __restrict__ out) {
    __shared__ float As[16][34];
    __shared__ float Bs[16][68];
    int rowBase = blockIdx.y * 32;
    int tid = threadIdx.x;
    int tx = tid & 15, ty = tid >> 4;
    float acc[2][4] = {};
    for (int k0 = 0; k0 < H * E; k0 += 16) {
        if (tid < 128) {
            int r = tid >> 2, ch = tid & 3;
            float4 v = *(const float4*)(g_feat + (size_t)(rowBase + r) * (H * E) + k0 + 4 * ch);
            As[4 * ch + 0][r] = v.x; As[4 * ch + 1][r] = v.y;
            As[4 * ch + 2][r] = v.z; As[4 * ch + 3][r] = v.w;
        }
        {
            int r = tid >> 4, ch = tid & 15;
            float4 v = *(const float4*)(W_act + (size_t)(k0 + r) * A_ + 4 * ch);
            *(float4*)&Bs[r][4 * ch] = v;
        }
        __syncthreads();
#pragma unroll
        for (int kk = 0; kk < 16; kk++) {
            float a0 = As[kk][ty * 2], a1 = As[kk][ty * 2 + 1];
            float4 bv = *(float4*)&Bs[kk][tx * 4];
            acc[0][0] += a0 * bv.x; acc[0][1] += a0 * bv.y;
            acc[0][2] += a0 * bv.z; acc[0][3] += a0 * bv.w;
            acc[1][0] += a1 * bv.x; acc[1][1] += a1 * bv.y;
            acc[1][2] += a1 * bv.z; acc[1][3] += a1 * bv.w;
        }
        __syncthreads();
    }
    float4 bias = *(const float4*)(b_act + tx * 4);
#pragma unroll
    for (int i = 0; i < 2; i++) {
        int r = rowBase + ty * 2 + i;
        float4 v = make_float4(acc[i][0] + bias.x, acc[i][1] + bias.y,
                               acc[i][2] + bias.z, acc[i][3] + bias.w);
        *(float4*)(out + (size_t)r * A_ + tx * 4) = v;
    }
}

extern "C" void kernel_launch(void* const* d_in, const int* in_sizes, int n_in,
                              void* d_out, int out_size) {
    const float* x     = (const float*)d_in[0];
    const int*   adj   = (const int*)d_in[1];
    const float* W     = (const float*)d_in[2];
    const float* a1    = (const float*)d_in[3];
    const float* a2    = (const float*)d_in[4];
    const float* W_act = (const float*)d_in[5];
    const float* b_act = (const float*)d_in[6];
    float* out = (float*)d_out;

    cudaFuncSetAttribute(wh_gemm_mma, cudaFuncAttributeMaxDynamicSharedMemorySize, GEMM_SMEM);
    cudaFuncSetAttribute(att_gemm_mma, cudaFuncAttributeMaxDynamicSharedMemorySize, ATT_SMEM);

    pack_adj<<<(Bb * Nn * Nn) / 256, 256>>>(adj);
    wh_gemm_mma<<<dim3(E / 128, BN_ROWS / 128, H), 256, GEMM_SMEM>>>(x, W);
    compute_f<<<(H * BN_ROWS) / 8, 256>>>(a1, a2);
    att_gemm_mma<<<dim3(E / 128, Nn / 128, H * Bb), 256, ATT_SMEM>>>();
    final_gemm<<<dim3(1, BN_ROWS / 32), 256>>>(W_act, b_act, out);
}

// round 8
// speedup vs baseline: 1.2104x; 1.2104x over previous
#include <cuda_runtime.h>
#include <cuda_bf16.h>
#include <math.h>
#include <stdint.h>

#define H 4
#define Bb 8
#define Nn 1024
#define INF_ 1024
#define E 256
#define A_ 64
#define BN_ROWS 8192        /* B*N */
#define ALPHA 0.2f
#define PITCH 136           /* smem row pitch in 32-bit words, conflict-free */

// ---- scratch (static device memory; no runtime allocation) ----
__device__ float g_Wh[H * BN_ROWS * E];                 // 32 MB  [h][row][e]
__device__ float g_f1[H * BN_ROWS];
__device__ float g_E1[H * BN_ROWS];
__device__ float g_F1[H * BN_ROWS];
__device__ float4 g_pack[H * BN_ROWS];                  // (f2, exp(f2), exp(.2 f2), 0)
__device__ unsigned g_adjbits[Bb * Nn * (Nn / 32)];     // 1 MB packed adjacency
__device__ float g_feat[(size_t)BN_ROWS * H * E];       // 32 MB [row][h*E+e]

// ---- bf16x3 helpers ----
__device__ __forceinline__ uint32_t bfpack(float lo, float hi) {
    uint32_t r;
    asm("cvt.rn.bf16x2.f32 %0, %1, %2;" : "=r"(r) : "f"(hi), "f"(lo));
    return r;
}
__device__ __forceinline__ float bfres(float v) {
    __nv_bfloat16 hb = __float2bfloat16(v);
    return v - __bfloat162float(hb);
}
__device__ __forceinline__ void mma16(float c[4], const uint32_t a[4], const uint32_t b[2]) {
    asm volatile(
        "mma.sync.aligned.m16n8k16.row.col.f32.bf16.bf16.f32 "
        "{%0,%1,%2,%3}, {%4,%5,%6,%7}, {%8,%9}, {%0,%1,%2,%3};"
        : "+f"(c[0]), "+f"(c[1]), "+f"(c[2]), "+f"(c[3])
        : "r"(a[0]), "r"(a[1]), "r"(a[2]), "r"(a[3]), "r"(b[0]), "r"(b[1]));
}
// one k16 step over a 128x128 tile set: 16 mma x 3 passes (bf16x3)
__device__ __forceinline__ void k16_step(const uint32_t (*AH)[PITCH], const uint32_t (*AL)[PITCH],
                                         const uint32_t (*BH)[PITCH], const uint32_t (*BL)[PITCH],
                                         int k2, int mw, int nw, int lq, int lr,
                                         float acc[4][4][4]) {
    uint32_t ah[4][4], al[4][4], bh[4][2], bl[4][2];
#pragma unroll
    for (int mt = 0; mt < 4; mt++) {
        int m0 = mw + 16 * mt + lr;
        ah[mt][0] = AH[k2 + lq][m0];     ah[mt][1] = AH[k2 + lq][m0 + 8];
        ah[mt][2] = AH[k2 + lq + 4][m0]; ah[mt][3] = AH[k2 + lq + 4][m0 + 8];
        al[mt][0] = AL[k2 + lq][m0];     al[mt][1] = AL[k2 + lq][m0 + 8];
        al[mt][2] = AL[k2 + lq + 4][m0]; al[mt][3] = AL[k2 + lq + 4][m0 + 8];
    }
#pragma unroll
    for (int nt = 0; nt < 4; nt++) {
        int n0 = nw + 8 * nt + lr;
        bh[nt][0] = BH[k2 + lq][n0]; bh[nt][1] = BH[k2 + lq + 4][n0];
        bl[nt][0] = BL[k2 + lq][n0]; bl[nt][1] = BL[k2 + lq + 4][n0];
    }
#pragma unroll
    for (int mt = 0; mt < 4; mt++)
#pragma unroll
        for (int nt = 0; nt < 4; nt++) mma16(acc[mt][nt], ah[mt], bh[nt]);
#pragma unroll
    for (int mt = 0; mt < 4; mt++)
#pragma unroll
        for (int nt = 0; nt < 4; nt++) mma16(acc[mt][nt], ah[mt], bl[nt]);
#pragma unroll
    for (int mt = 0; mt < 4; mt++)
#pragma unroll
        for (int nt = 0; nt < 4; nt++) mma16(acc[mt][nt], al[mt], bh[nt]);
}

#define GEMM_SMEM (128 * PITCH * 4)             /* 4 arrays x 2 stages x 16 rows */
#define ATT_SMEM  (GEMM_SMEM + 256 * 4)

// ============================================================
// K0: pack adjacency int32 -> bitmask
// ============================================================
__global__ void pack_adj(const int* __restrict__ adj) {
    int idx = blockIdx.x * blockDim.x + threadIdx.x;
    unsigned m = __ballot_sync(0xffffffffu, adj[idx] > 0);
    if ((idx & 31) == 0) g_adjbits[idx >> 5] = m;
}

// ============================================================
// K1: Wh = x @ W[h], bf16x3 mma, BK=32 double-buffered.
// grid (E/128=2, BN/128=64, H=4), 256 thr.
// ============================================================
__global__ void __launch_bounds__(256, 2) wh_gemm_mma(const float* __restrict__ x,
                                                      const float* __restrict__ W) {
    extern __shared__ uint32_t smw[];
    uint32_t (*AH)[PITCH] = (uint32_t (*)[PITCH])smw;
    uint32_t (*AL)[PITCH] = (uint32_t (*)[PITCH])(smw + 32 * PITCH);
    uint32_t (*BH)[PITCH] = (uint32_t (*)[PITCH])(smw + 64 * PITCH);
    uint32_t (*BL)[PITCH] = (uint32_t (*)[PITCH])(smw + 96 * PITCH);
    int h = blockIdx.z;
    int rowBase = blockIdx.y * 128;
    int colBase = blockIdx.x * 128;
    int tid = threadIdx.x, lane = tid & 31, wid = tid >> 5;
    int lq = lane & 3, lr = lane >> 2;
    int mw = (wid & 1) * 64, nw = (wid >> 1) * 32;

    int am = tid & 127, jp = tid >> 7;          // A: row am, k in [16jp, 16jp+16)
    int pk = tid >> 5;                          // B: k2 rows pk, pk+8
    int n4 = (lane) * 4;

    const float* Ap = x + (size_t)(rowBase + am) * INF_ + 16 * jp;
    const float* Bp = W + (size_t)h * INF_ * E + colBase + n4;

#define WH_STORE(SB, A0, A1, A2, A3, B0, B1, B2, B3)                          \
    do {                                                                      \
        int kr = (SB) + 8 * jp;                                               \
        AH[kr + 0][am] = bfpack(A0.x, A0.y);                                  \
        AL[kr + 0][am] = bfpack(bfres(A0.x), bfres(A0.y));                    \
        AH[kr + 1][am] = bfpack(A0.z, A0.w);                                  \
        AL[kr + 1][am] = bfpack(bfres(A0.z), bfres(A0.w));                    \
        AH[kr + 2][am] = bfpack(A1.x, A1.y);                                  \
        AL[kr + 2][am] = bfpack(bfres(A1.x), bfres(A1.y));                    \
        AH[kr + 3][am] = bfpack(A1.z, A1.w);                                  \
        AL[kr + 3][am] = bfpack(bfres(A1.z), bfres(A1.w));                    \
        AH[kr + 4][am] = bfpack(A2.x, A2.y);                                  \
        AL[kr + 4][am] = bfpack(bfres(A2.x), bfres(A2.y));                    \
        AH[kr + 5][am] = bfpack(A2.z, A2.w);                                  \
        AL[kr + 5][am] = bfpack(bfres(A2.z), bfres(A2.w));                    \
        AH[kr + 6][am] = bfpack(A3.x, A3.y);                                  \
        AL[kr + 6][am] = bfpack(bfres(A3.x), bfres(A3.y));                    \
        AH[kr + 7][am] = bfpack(A3.z, A3.w);                                  \
        AL[kr + 7][am] = bfpack(bfres(A3.z), bfres(A3.w));                    \
        int b0r = (SB) + pk, b1r = (SB) + pk + 8;                             \
        BH[b0r][n4 + 0] = bfpack(B0.x, B1.x);                                 \
        BH[b0r][n4 + 1] = bfpack(B0.y, B1.y);                                 \
        BH[b0r][n4 + 2] = bfpack(B0.z, B1.z);                                 \
        BH[b0r][n4 + 3] = bfpack(B0.w, B1.w);                                 \
        BL[b0r][n4 + 0] = bfpack(bfres(B0.x), bfres(B1.x));                   \
        BL[b0r][n4 + 1] = bfpack(bfres(B0.y), bfres(B1.y));                   \
        BL[b0r][n4 + 2] = bfpack(bfres(B0.z), bfres(B1.z));                   \
        BL[b0r][n4 + 3] = bfpack(bfres(B0.w), bfres(B1.w));                   \
        BH[b1r][n4 + 0] = bfpack(B2.x, B3.x);                                 \
        BH[b1r][n4 + 1] = bfpack(B2.y, B3.y);                                 \
        BH[b1r][n4 + 2] = bfpack(B2.z, B3.z);                                 \
        BH[b1r][n4 + 3] = bfpack(B2.w, B3.w);                                 \
        BL[b1r][n4 + 0] = bfpack(bfres(B2.x), bfres(B3.x));                   \
        BL[b1r][n4 + 1] = bfpack(bfres(B2.y), bfres(B3.y));                   \
        BL[b1r][n4 + 2] = bfpack(bfres(B2.z), bfres(B3.z));                   \
        BL[b1r][n4 + 3] = bfpack(bfres(B2.w), bfres(B3.w));                   \
    } while (0)

    // prologue: fill stage 0 (k 0..31)
    {
        float4 a0 = *(const float4*)(Ap + 0);
        float4 a1 = *(const float4*)(Ap + 4);
        float4 a2 = *(const float4*)(Ap + 8);
        float4 a3 = *(const float4*)(Ap + 12);
        float4 b0 = *(const float4*)(Bp + (size_t)(2 * pk) * E);
        float4 b1 = *(const float4*)(Bp + (size_t)(2 * pk + 1) * E);
        float4 b2 = *(const float4*)(Bp + (size_t)(2 * pk + 16) * E);
        float4 b3 = *(const float4*)(Bp + (size_t)(2 * pk + 17) * E);
        WH_STORE(0, a0, a1, a2, a3, b0, b1, b2, b3);
    }
    __syncthreads();

    float acc[4][4][4] = {};
    for (int c = 0; c < 32; c++) {
        int cb = c & 1, nb = cb ^ 1;
        int k0n = (c + 1) * 32;
        float4 a0, a1, a2, a3, b0, b1, b2, b3;
        if (c < 31) {
            a0 = *(const float4*)(Ap + k0n);
            a1 = *(const float4*)(Ap + k0n + 4);
            b0 = *(const float4*)(Bp + (size_t)(k0n + 2 * pk) * E);
            b1 = *(const float4*)(Bp + (size_t)(k0n + 2 * pk + 1) * E);
        }
        k16_step(AH + cb * 16, AL + cb * 16, BH + cb * 16, BL + cb * 16, 0, mw, nw, lq, lr, acc);
        if (c < 31) {
            a2 = *(const float4*)(Ap + k0n + 8);
            a3 = *(const float4*)(Ap + k0n + 12);
            b2 = *(const float4*)(Bp + (size_t)(k0n + 2 * pk + 16) * E);
            b3 = *(const float4*)(Bp + (size_t)(k0n + 2 * pk + 17) * E);
        }
        k16_step(AH + cb * 16, AL + cb * 16, BH + cb * 16, BL + cb * 16, 8, mw, nw, lq, lr, acc);
        if (c < 31) WH_STORE(nb * 16, a0, a1, a2, a3, b0, b1, b2, b3);
        __syncthreads();
    }
#undef WH_STORE

    float* Cp = g_Wh + (size_t)h * BN_ROWS * E;
#pragma unroll
    for (int mt = 0; mt < 4; mt++) {
        int r = rowBase + mw + 16 * mt + lr;
#pragma unroll
        for (int nt = 0; nt < 4; nt++) {
            int cc = colBase + nw + 8 * nt + 2 * lq;
            *(float2*)(Cp + (size_t)r * E + cc) = make_float2(acc[mt][nt][0], acc[mt][nt][1]);
            *(float2*)(Cp + (size_t)(r + 8) * E + cc) = make_float2(acc[mt][nt][2], acc[mt][nt][3]);
        }
    }
}

// ============================================================
// K2: f1/f2 = Wh . a1/a2 + factored exps. Warp per row.
// ============================================================
__global__ void compute_f(const float* __restrict__ a1, const float* __restrict__ a2) {
    int r = (blockIdx.x * blockDim.x + threadIdx.x) >> 5;
    int lane = threadIdx.x & 31;
    int h = r >> 13;
    const float* wh = g_Wh + (size_t)r * E;
    const float* a1p = a1 + h * E;
    const float* a2p = a2 + h * E;
    float s1 = 0.f, s2 = 0.f;
#pragma unroll
    for (int i = 0; i < 8; i++) {
        int e = lane + i * 32;
        float v = wh[e];
        s1 += v * a1p[e];
        s2 += v * a2p[e];
    }
#pragma unroll
    for (int o = 16; o > 0; o >>= 1) {
        s1 += __shfl_xor_sync(0xffffffffu, s1, o);
        s2 += __shfl_xor_sync(0xffffffffu, s2, o);
    }
    if (lane == 0) {
        g_f1[r] = s1;
        g_E1[r] = __expf(s1);
        g_F1[r] = __expf(ALPHA * s1);
        g_pack[r] = make_float4(s2, __expf(s2), __expf(ALPHA * s2), 0.f);
    }
}

// ============================================================
// K3: h' = att @ Wh_b, bf16x3 mma, BK=32; att generated on the fly
// (unnormalized), row sums in regs, normalize + elu in epilogue.
// grid (E/128=2, Nn/128=8, H*Bb=32), 256 thr.
// ============================================================
__global__ void __launch_bounds__(256, 2) att_gemm_mma() {
    extern __shared__ uint32_t smw[];
    uint32_t (*AH)[PITCH] = (uint32_t (*)[PITCH])smw;
    uint32_t (*AL)[PITCH] = (uint32_t (*)[PITCH])(smw + 32 * PITCH);
    uint32_t (*BH)[PITCH] = (uint32_t (*)[PITCH])(smw + 64 * PITCH);
    uint32_t (*BL)[PITCH] = (uint32_t (*)[PITCH])(smw + 96 * PITCH);
    float* Ssum = (float*)(smw + 128 * PITCH);     // [2][128]
    int hb = blockIdx.z;
    int h = hb >> 3, b = hb & 7;
    int rowBase = blockIdx.y * 128;
    int colBase = blockIdx.x * 128;
    int base = h * BN_ROWS + b * Nn;
    int tid = threadIdx.x, lane = tid & 31, wid = tid >> 5;
    int lq = lane & 3, lr = lane >> 2;
    int mw = (wid & 1) * 64, nw = (wid >> 1) * 32;

    // generator: fixed row ig, j in [16jp, 16jp+16) per stage
    int ig = tid & 127;
    int jp = tid >> 7;
    int gi = base + rowBase + ig;
    float f1v = g_f1[gi], E1v = g_E1[gi], F1v = g_F1[gi];
    const unsigned* awp = g_adjbits + (size_t)(b * Nn + rowBase + ig) * (Nn / 32);
    float rsum = 0.f;

    int pk = tid >> 5;
    int n4 = lane * 4;
    const float* Bp = g_Wh + ((size_t)h * BN_ROWS + b * Nn) * E + colBase + n4;

#define GENB(SB, K0)                                                          \
    do {                                                                      \
        unsigned wb = awp[(K0) >> 5] >> (16 * jp);                            \
        _Pragma("unroll")                                                     \
        for (int t = 0; t < 8; t++) {                                         \
            int j = (K0) + 16 * jp + 2 * t;                                   \
            float4 p0 = g_pack[base + j];                                     \
            float4 p1 = g_pack[base + j + 1];                                 \
            float s0 = f1v + p0.x;                                            \
            float v0 = ((wb >> (2 * t)) & 1u)                                 \
                           ? ((s0 > 0.f) ? E1v * p0.y : F1v * p0.z) : 0.f;    \
            float s1 = f1v + p1.x;                                            \
            float v1 = ((wb >> (2 * t + 1)) & 1u)                             \
                           ? ((s1 > 0.f) ? E1v * p1.y : F1v * p1.z) : 0.f;    \
            rsum += v0 + v1;                                                  \
            AH[(SB) + 8 * jp + t][ig] = bfpack(v0, v1);                       \
            AL[(SB) + 8 * jp + t][ig] = bfpack(bfres(v0), bfres(v1));         \
        }                                                                     \
    } while (0)

#define BSTORE(SB, B0, B1, B2, B3)                                           \
    do {                                                                      \
        int b0r = (SB) + pk, b1r = (SB) + pk + 8;                             \
        BH[b0r][n4 + 0] = bfpack(B0.x, B1.x);                                 \
        BH[b0r][n4 + 1] = bfpack(B0.y, B1.y);                                 \
        BH[b0r][n4 + 2] = bfpack(B0.z, B1.z);                                 \
        BH[b0r][n4 + 3] = bfpack(B0.w, B1.w);                                 \
        BL[b0r][n4 + 0] = bfpack(bfres(B0.x), bfres(B1.x));                   \
        BL[b0r][n4 + 1] = bfpack(bfres(B0.y), bfres(B1.y));                   \
        BL[b0r][n4 + 2] = bfpack(bfres(B0.z), bfres(B1.z));                   \
        BL[b0r][n4 + 3] = bfpack(bfres(B0.w), bfres(B1.w));                   \
        BH[b1r][n4 + 0] = bfpack(B2.x, B3.x);                                 \
        BH[b1r][n4 + 1] = bfpack(B2.y, B3.y);                                 \
        BH[b1r][n4 + 2] = bfpack(B2.z, B3.z);                                 \
        BH[b1r][n4 + 3] = bfpack(B2.w, B3.w);                                 \
        BL[b1r][n4 + 0] = bfpack(bfres(B2.x), bfres(B3.x));                   \
        BL[b1r][n4 + 1] = bfpack(bfres(B2.y), bfres(B3.y));                   \
        BL[b1r][n4 + 2] = bfpack(bfres(B2.z), bfres(B3.z));                   \
        BL[b1r][n4 + 3] = bfpack(bfres(B2.w), bfres(B3.w));                   \
    } while (0)

    // prologue: stage 0
    {
        GENB(0, 0);
        float4 b0 = *(const float4*)(Bp + (size_t)(2 * pk) * E);
        float4 b1 = *(const float4*)(Bp + (size_t)(2 * pk + 1) * E);
        float4 b2 = *(const float4*)(Bp + (size_t)(2 * pk + 16) * E);
        float4 b3 = *(const float4*)(Bp + (size_t)(2 * pk + 17) * E);
        BSTORE(0, b0, b1, b2, b3);
    }
    __syncthreads();

    float acc[4][4][4] = {};
    for (int c = 0; c < 32; c++) {
        int cb = c & 1, nb = cb ^ 1;
        int k0n = (c + 1) * 32;
        float4 b0, b1, b2, b3;
        if (c < 31) {
            b0 = *(const float4*)(Bp + (size_t)(k0n + 2 * pk) * E);
            b1 = *(const float4*)(Bp + (size_t)(k0n + 2 * pk + 1) * E);
            b2 = *(const float4*)(Bp + (size_t)(k0n + 2 * pk + 16) * E);
            b3 = *(const float4*)(Bp + (size_t)(k0n + 2 * pk + 17) * E);
        }
        k16_step(AH + cb * 16, AL + cb * 16, BH + cb * 16, BL + cb * 16, 0, mw, nw, lq, lr, acc);
        if (c < 31) GENB(nb * 16, k0n);
        k16_step(AH + cb * 16, AL + cb * 16, BH + cb * 16, BL + cb * 16, 8, mw, nw, lq, lr, acc);
        if (c < 31) BSTORE(nb * 16, b0, b1, b2, b3);
        __syncthreads();
    }
#undef GENB
#undef BSTORE

    Ssum[jp * 128 + ig] = rsum;
    __syncthreads();

#pragma unroll
    for (int mt = 0; mt < 4; mt++) {
        int rl = mw + 16 * mt + lr;
        float S0 = Ssum[rl] + Ssum[128 + rl];
        float S8 = Ssum[rl + 8] + Ssum[128 + rl + 8];
        float sc0 = (S0 > 0.f) ? (1.0f / S0) : 0.f;
        float sc8 = (S8 > 0.f) ? (1.0f / S8) : 0.f;
        float* f0 = g_feat + (size_t)(b * Nn + rowBase + rl) * (H * E) + h * E + colBase;
        float* f8 = g_feat + (size_t)(b * Nn + rowBase + rl + 8) * (H * E) + h * E + colBase;
#pragma unroll
        for (int nt = 0; nt < 4; nt++) {
            int cc = nw + 8 * nt + 2 * lq;
            float v0 = acc[mt][nt][0] * sc0;
            float v1 = acc[mt][nt][1] * sc0;
            float v2 = acc[mt][nt][2] * sc8;
            float v3 = acc[mt][nt][3] * sc8;
            v0 = (v0 > 0.f) ? v0 : expm1f(v0);
            v1 = (v1 > 0.f) ? v1 : expm1f(v1);
            v2 = (v2 > 0.f) ? v2 : expm1f(v2);
            v3 = (v3 > 0.f) ? v3 : expm1f(v3);
            *(float2*)(f0 + cc) = make_float2(v0, v1);
            *(float2*)(f8 + cc) = make_float2(v2, v3);
        }
    }
}

// ============================================================
// K5: out (8192x64) = feat (8192x1024) @ W_act (1024x64) + b_act
// BM=32 (256 blocks), 256 thr, 2x4 per thread
// ============================================================
__global__ void __launch_bounds__(256) final_gemm(const float* __restrict__ W_act,
                                                  const float* __restrict__ b_act,
                                                  float* __restrict__ out) {
    __shared__ float As[16][34];
    __shared__ float Bs[16][68];
    int rowBase = blockIdx.y * 32;
    int tid = threadIdx.x;
    int tx = tid & 15, ty = tid >> 4;
    float acc[2][4] = {};
    for (int k0 = 0; k0 < H * E; k0 += 16) {
        if (tid < 128) {
            int r = tid >> 2, ch = tid & 3;
            float4 v = *(const float4*)(g_feat + (size_t)(rowBase + r) * (H * E) + k0 + 4 * ch);
            As[4 * ch + 0][r] = v.x; As[4 * ch + 1][r] = v.y;
            As[4 * ch + 2][r] = v.z; As[4 * ch + 3][r] = v.w;
        }
        {
            int r = tid >> 4, ch = tid & 15;
            float4 v = *(const float4*)(W_act + (size_t)(k0 + r) * A_ + 4 * ch);
            *(float4*)&Bs[r][4 * ch] = v;
        }
        __syncthreads();
#pragma unroll
        for (int kk = 0; kk < 16; kk++) {
            float a0 = As[kk][ty * 2], a1v = As[kk][ty * 2 + 1];
            float4 bv = *(float4*)&Bs[kk][tx * 4];
            acc[0][0] += a0 * bv.x; acc[0][1] += a0 * bv.y;
            acc[0][2] += a0 * bv.z; acc[0][3] += a0 * bv.w;
            acc[1][0] += a1v * bv.x; acc[1][1] += a1v * bv.y;
            acc[1][2] += a1v * bv.z; acc[1][3] += a1v * bv.w;
        }
        __syncthreads();
    }
    float4 bias = *(const float4*)(b_act + tx * 4);
#pragma unroll
    for (int i = 0; i < 2; i++) {
        int r = rowBase + ty * 2 + i;
        float4 v = make_float4(acc[i][0] + bias.x, acc[i][1] + bias.y,
                               acc[i][2] + bias.z, acc[i][3] + bias.w);
        *(float4*)(out + (size_t)r * A_ + tx * 4) = v;
    }
}

extern "C" void kernel_launch(void* const* d_in, const int* in_sizes, int n_in,
                              void* d_out, int out_size) {
    const float* x     = (const float*)d_in[0];
    const int*   adj   = (const int*)d_in[1];
    const float* W     = (const float*)d_in[2];
    const float* a1    = (const float*)d_in[3];
    const float* a2    = (const float*)d_in[4];
    const float* W_act = (const float*)d_in[5];
    const float* b_act = (const float*)d_in[6];
    float* out = (float*)d_out;

    cudaFuncSetAttribute(wh_gemm_mma, cudaFuncAttributeMaxDynamicSharedMemorySize, GEMM_SMEM);
    cudaFuncSetAttribute(att_gemm_mma, cudaFuncAttributeMaxDynamicSharedMemorySize, ATT_SMEM);

    pack_adj<<<(Bb * Nn * Nn) / 256, 256>>>(adj);
    wh_gemm_mma<<<dim3(E / 128, BN_ROWS / 128, H), 256, GEMM_SMEM>>>(x, W);
    compute_f<<<(H * BN_ROWS) / 8, 256>>>(a1, a2);
    att_gemm_mma<<<dim3(E / 128, Nn / 128, H * Bb), 256, ATT_SMEM>>>();
    final_gemm<<<dim3(1, BN_ROWS / 32), 256>>>(W_act, b_act, out);
}